// round 1
// baseline (speedup 1.0000x reference)
#include <cuda_runtime.h>
#include <cuda_bf16.h>
#include <math.h>

#define NN 100000
#define EE 1600000
// layer1: F_IN=128, HEADS=8, HID=8 (64 out), layer2: 64 -> 16
#define NEG_SLOPE 0.2f

// ---------------- scratch (device globals; no allocation allowed) ----------------
__device__ float g_h1[NN * 64];      // layer1 node features after GEMM
__device__ float g_as1[NN * 8];      // alpha_src per node/head
__device__ float g_ad1[NN * 8];      // alpha_dst per node/head
__device__ float g_e[EE * 8];        // per-edge logits (layer1); reused (E floats) for layer2
__device__ float g_m[NN * 8];        // segment max
__device__ float g_den[NN * 8];      // segment exp-sum
__device__ float g_out1[NN * 64];    // layer1 aggregation -> ELU output (in place)
__device__ float g_g2[NN * 16];      // layer2 GEMM output
__device__ float g_as2[NN];
__device__ float g_ad2[NN];
__device__ float g_m2[NN];
__device__ float g_den2[NN];

// ---------------- helpers ----------------
__device__ __forceinline__ void atomicMaxFloat(float* addr, float val) {
    // classic monotonic-bits trick; correct for mixed signs
    if (val >= 0.0f) {
        atomicMax((int*)addr, __float_as_int(val));
    } else {
        atomicMin((unsigned int*)addr, __float_as_uint(val));
    }
}

// ---------------- K0: init accumulators (re-run every graph replay) ----------------
__global__ void k0_init(float* __restrict__ out) {
    int i = blockIdx.x * blockDim.x + threadIdx.x;
    if (i < NN * 64) g_out1[i] = 0.0f;
    if (i < NN * 16) out[i] = 0.0f;
    if (i < NN * 8) { g_den[i] = 0.0f; g_m[i] = -INFINITY; }
    if (i < NN)     { g_den2[i] = 0.0f; g_m2[i] = -INFINITY; }
}

// ---------------- K1: h1 = x @ W1  (+ per-head attention logits) ----------------
__global__ void __launch_bounds__(256) k1_gemm1(
    const float* __restrict__ x, const float* __restrict__ W1,
    const float* __restrict__ a1s, const float* __restrict__ a1d)
{
    __shared__ float sW[128 * 64];
    __shared__ float sA[128];   // [0:64) a1_src flat, [64:128) a1_dst flat
    for (int i = threadIdx.x; i < 128 * 64; i += blockDim.x) sW[i] = W1[i];
    for (int i = threadIdx.x; i < 128; i += blockDim.x)
        sA[i] = (i < 64) ? a1s[i] : a1d[i - 64];
    __syncthreads();

    int row = blockIdx.x * blockDim.x + threadIdx.x;
    if (row >= NN) return;

    float acc[64];
#pragma unroll
    for (int j = 0; j < 64; j++) acc[j] = 0.0f;

    const float4* x4 = (const float4*)(x + (size_t)row * 128);
#pragma unroll 1
    for (int kc = 0; kc < 32; kc++) {
        float4 xv = __ldg(x4 + kc);
#pragma unroll
        for (int t = 0; t < 4; t++) {
            float xs = (t == 0) ? xv.x : (t == 1) ? xv.y : (t == 2) ? xv.z : xv.w;
            const float4* wrow = (const float4*)(sW + (kc * 4 + t) * 64);
#pragma unroll
            for (int j4 = 0; j4 < 16; j4++) {
                float4 w = wrow[j4];
                acc[j4 * 4 + 0] += xs * w.x;
                acc[j4 * 4 + 1] += xs * w.y;
                acc[j4 * 4 + 2] += xs * w.z;
                acc[j4 * 4 + 3] += xs * w.w;
            }
        }
    }

    float4* h1o = (float4*)(g_h1 + (size_t)row * 64);
#pragma unroll
    for (int j4 = 0; j4 < 16; j4++)
        h1o[j4] = make_float4(acc[j4 * 4], acc[j4 * 4 + 1], acc[j4 * 4 + 2], acc[j4 * 4 + 3]);

#pragma unroll
    for (int h = 0; h < 8; h++) {
        float s = 0.0f, d = 0.0f;
#pragma unroll
        for (int q = 0; q < 8; q++) {
            s += acc[h * 8 + q] * sA[h * 8 + q];
            d += acc[h * 8 + q] * sA[64 + h * 8 + q];
        }
        g_as1[row * 8 + h] = s;
        g_ad1[row * 8 + h] = d;
    }
}

// ---------------- K2: edge pass 1 (layer1): e + segment max ----------------
__global__ void k2_edge_max(const int* __restrict__ src, const int* __restrict__ dst) {
    int t = blockIdx.x * blockDim.x + threadIdx.x;   // over E*8
    if (t >= EE * 8) return;
    int e = t >> 3, h = t & 7;
    int s = src[e], d = dst[e];
    float v = g_as1[s * 8 + h] + g_ad1[d * 8 + h];
    v = (v >= 0.0f) ? v : NEG_SLOPE * v;
    g_e[t] = v;
    atomicMaxFloat(&g_m[d * 8 + h], v);
}

// ---------------- K3: edge pass 2 (layer1): unnormalized weighted scatter ----------------
__global__ void k3_edge_acc(const int* __restrict__ src, const int* __restrict__ dst) {
    int t = blockIdx.x * blockDim.x + threadIdx.x;   // over E*8 (8 threads per edge = heads)
    if (t >= EE * 8) return;
    int e = t >> 3, h = t & 7;
    int s = src[e], d = dst[e];
    float ex = __expf(g_e[t] - g_m[d * 8 + h]);
    atomicAdd(&g_den[d * 8 + h], ex);
    const float4* hv = (const float4*)(g_h1 + (size_t)s * 64 + h * 8);
    float4 v0 = hv[0], v1 = hv[1];
    float* o = g_out1 + (size_t)d * 64 + h * 8;
    atomicAdd(o + 0, ex * v0.x);
    atomicAdd(o + 1, ex * v0.y);
    atomicAdd(o + 2, ex * v0.z);
    atomicAdd(o + 3, ex * v0.w);
    atomicAdd(o + 4, ex * v1.x);
    atomicAdd(o + 5, ex * v1.y);
    atomicAdd(o + 6, ex * v1.z);
    atomicAdd(o + 7, ex * v1.w);
}

// ---------------- K4: layer1 node finalize: normalize + bias + ELU ----------------
__global__ void k4_node1(const float* __restrict__ b1) {
    int i = blockIdx.x * blockDim.x + threadIdx.x;   // over N*64
    if (i >= NN * 64) return;
    int n = i >> 6, c = i & 63, h = c >> 3;
    float den = g_den[n * 8 + h];
    float v = (den > 0.0f) ? (g_out1[i] / den) : 0.0f;
    v += b1[c];
    v = (v > 0.0f) ? v : (__expf(v) - 1.0f);
    g_out1[i] = v;
}

// ---------------- K5: g2 = elu_h @ W2 (+ layer2 attention logits) ----------------
__global__ void __launch_bounds__(256) k5_gemm2(
    const float* __restrict__ W2, const float* __restrict__ a2s,
    const float* __restrict__ a2d)
{
    __shared__ float sW[64 * 16];
    __shared__ float sA[32];
    for (int i = threadIdx.x; i < 64 * 16; i += blockDim.x) sW[i] = W2[i];
    for (int i = threadIdx.x; i < 32; i += blockDim.x)
        sA[i] = (i < 16) ? a2s[i] : a2d[i - 16];
    __syncthreads();

    int row = blockIdx.x * blockDim.x + threadIdx.x;
    if (row >= NN) return;

    float acc[16];
#pragma unroll
    for (int j = 0; j < 16; j++) acc[j] = 0.0f;

    const float4* x4 = (const float4*)(g_out1 + (size_t)row * 64);
#pragma unroll 1
    for (int kc = 0; kc < 16; kc++) {
        float4 xv = x4[kc];
#pragma unroll
        for (int t = 0; t < 4; t++) {
            float xs = (t == 0) ? xv.x : (t == 1) ? xv.y : (t == 2) ? xv.z : xv.w;
            const float4* wrow = (const float4*)(sW + (kc * 4 + t) * 16);
#pragma unroll
            for (int j4 = 0; j4 < 4; j4++) {
                float4 w = wrow[j4];
                acc[j4 * 4 + 0] += xs * w.x;
                acc[j4 * 4 + 1] += xs * w.y;
                acc[j4 * 4 + 2] += xs * w.z;
                acc[j4 * 4 + 3] += xs * w.w;
            }
        }
    }

    float4* go = (float4*)(g_g2 + (size_t)row * 16);
#pragma unroll
    for (int j4 = 0; j4 < 4; j4++)
        go[j4] = make_float4(acc[j4 * 4], acc[j4 * 4 + 1], acc[j4 * 4 + 2], acc[j4 * 4 + 3]);

    float s = 0.0f, d = 0.0f;
#pragma unroll
    for (int j = 0; j < 16; j++) { s += acc[j] * sA[j]; d += acc[j] * sA[16 + j]; }
    g_as2[row] = s;
    g_ad2[row] = d;
}

// ---------------- K6: edge pass 1 (layer2) ----------------
__global__ void k6_edge_max2(const int* __restrict__ src, const int* __restrict__ dst) {
    int e = blockIdx.x * blockDim.x + threadIdx.x;
    if (e >= EE) return;
    int s = src[e], d = dst[e];
    float v = g_as2[s] + g_ad2[d];
    v = (v >= 0.0f) ? v : NEG_SLOPE * v;
    g_e[e] = v;
    atomicMaxFloat(&g_m2[d], v);
}

// ---------------- K7: edge pass 2 (layer2): scatter into d_out ----------------
__global__ void k7_edge_acc2(const int* __restrict__ src, const int* __restrict__ dst,
                             float* __restrict__ out) {
    int t = blockIdx.x * blockDim.x + threadIdx.x;   // over E*4 (4 threads/edge, 4 cols each)
    if (t >= EE * 4) return;
    int e = t >> 2, q = t & 3;
    int s = src[e], d = dst[e];
    float ex = __expf(g_e[e] - g_m2[d]);
    if (q == 0) atomicAdd(&g_den2[d], ex);
    float4 v = ((const float4*)(g_g2 + (size_t)s * 16))[q];
    float* o = out + (size_t)d * 16 + q * 4;
    atomicAdd(o + 0, ex * v.x);
    atomicAdd(o + 1, ex * v.y);
    atomicAdd(o + 2, ex * v.z);
    atomicAdd(o + 3, ex * v.w);
}

// ---------------- K8: layer2 finalize: normalize + bias + log_softmax ----------------
__global__ void k8_node2(const float* __restrict__ b2, float* __restrict__ out) {
    int n = blockIdx.x * blockDim.x + threadIdx.x;
    if (n >= NN) return;
    float den = g_den2[n];
    float inv = (den > 0.0f) ? (1.0f / den) : 0.0f;
    float z[16];
    float4* o4 = (float4*)(out + (size_t)n * 16);
#pragma unroll
    for (int j4 = 0; j4 < 4; j4++) {
        float4 v = o4[j4];
        z[j4 * 4 + 0] = v.x * inv + b2[j4 * 4 + 0];
        z[j4 * 4 + 1] = v.y * inv + b2[j4 * 4 + 1];
        z[j4 * 4 + 2] = v.z * inv + b2[j4 * 4 + 2];
        z[j4 * 4 + 3] = v.w * inv + b2[j4 * 4 + 3];
    }
    float mx = z[0];
#pragma unroll
    for (int j = 1; j < 16; j++) mx = fmaxf(mx, z[j]);
    float sum = 0.0f;
#pragma unroll
    for (int j = 0; j < 16; j++) sum += __expf(z[j] - mx);
    float lse = mx + logf(sum);
#pragma unroll
    for (int j4 = 0; j4 < 4; j4++)
        o4[j4] = make_float4(z[j4 * 4 + 0] - lse, z[j4 * 4 + 1] - lse,
                             z[j4 * 4 + 2] - lse, z[j4 * 4 + 3] - lse);
}

// ---------------- launcher ----------------
extern "C" void kernel_launch(void* const* d_in, const int* in_sizes, int n_in,
                              void* d_out, int out_size) {
    const float* x    = (const float*)d_in[0];
    const int*   ei   = (const int*)d_in[1];
    const float* W1   = (const float*)d_in[2];
    const float* a1s  = (const float*)d_in[3];
    const float* a1d  = (const float*)d_in[4];
    const float* b1   = (const float*)d_in[5];
    const float* W2   = (const float*)d_in[6];
    const float* a2s  = (const float*)d_in[7];
    const float* a2d  = (const float*)d_in[8];
    const float* b2   = (const float*)d_in[9];
    float* out = (float*)d_out;

    const int* src = ei;
    const int* dst = ei + EE;

    const int TB = 256;
    k0_init<<<(NN * 64 + TB - 1) / TB, TB>>>(out);
    k1_gemm1<<<(NN + TB - 1) / TB, TB>>>(x, W1, a1s, a1d);
    k2_edge_max<<<(EE * 8 + TB - 1) / TB, TB>>>(src, dst);
    k3_edge_acc<<<(EE * 8 + TB - 1) / TB, TB>>>(src, dst);
    k4_node1<<<(NN * 64 + TB - 1) / TB, TB>>>(b1);
    k5_gemm2<<<(NN + TB - 1) / TB, TB>>>(W2, a2s, a2d);
    k6_edge_max2<<<(EE + TB - 1) / TB, TB>>>(src, dst);
    k7_edge_acc2<<<(EE * 4 + TB - 1) / TB, TB>>>(src, dst, out);
    k8_node2<<<(NN + TB - 1) / TB, TB>>>(b2, out);
}

// round 3
// speedup vs baseline: 2.5446x; 2.5446x over previous
#include <cuda_runtime.h>
#include <cuda_bf16.h>
#include <math.h>

#define NN 100000
#define EE 1600000
#define NEG_SLOPE 0.2f
#define SCAN_B 512
#define NBLK ((NN + SCAN_B - 1) / SCAN_B)   // 196

// ---------------- scratch (device globals) ----------------
__device__ float g_h1[NN * 64];     // layer1 GEMM output [N,H*D]
__device__ float g_as1[NN * 8];
__device__ float g_ad1[NN * 8];
__device__ float g_out1[NN * 64];   // layer1 final (ELU'd)
__device__ float g_g2[NN * 16];     // layer2 GEMM output
__device__ float g_as2[NN];
__device__ float g_ad2[NN];
__device__ int   g_deg[NN];
__device__ int   g_off[NN];
__device__ int   g_pos[NN];
__device__ int   g_csr[EE];         // src node ids, grouped by dst
__device__ int   g_bsum[NBLK];
__device__ int   g_bscan[NBLK];

// ---------------- K0: zero degree histogram ----------------
__global__ void k0_init() {
    int i = blockIdx.x * blockDim.x + threadIdx.x;
    if (i < NN) g_deg[i] = 0;
}

// ---------------- CSR build ----------------
__global__ void k_hist(const int* __restrict__ dst) {
    int e = blockIdx.x * blockDim.x + threadIdx.x;
    if (e < EE) atomicAdd(&g_deg[dst[e]], 1);
}

__global__ void s1_scan() {
    __shared__ int sd[SCAN_B];
    int i = blockIdx.x * SCAN_B + threadIdx.x;
    int v = (i < NN) ? g_deg[i] : 0;
    sd[threadIdx.x] = v;
    __syncthreads();
    for (int ofs = 1; ofs < SCAN_B; ofs <<= 1) {
        int t = (threadIdx.x >= ofs) ? sd[threadIdx.x - ofs] : 0;
        __syncthreads();
        sd[threadIdx.x] += t;
        __syncthreads();
    }
    if (i < NN) g_off[i] = sd[threadIdx.x] - v;           // exclusive
    if (threadIdx.x == SCAN_B - 1) g_bsum[blockIdx.x] = sd[threadIdx.x];
}

__global__ void s2_scan() {
    __shared__ int sd[256];
    int t = threadIdx.x;
    int v = (t < NBLK) ? g_bsum[t] : 0;
    sd[t] = v;
    __syncthreads();
    for (int ofs = 1; ofs < 256; ofs <<= 1) {
        int u = (t >= ofs) ? sd[t - ofs] : 0;
        __syncthreads();
        sd[t] += u;
        __syncthreads();
    }
    if (t < NBLK) g_bscan[t] = sd[t] - v;                 // exclusive
}

__global__ void s3_apply() {
    int i = blockIdx.x * blockDim.x + threadIdx.x;
    if (i >= NN) return;
    int o = g_off[i] + g_bscan[i / SCAN_B];
    g_off[i] = o;
    g_pos[i] = o;
}

__global__ void k_scatter(const int* __restrict__ src, const int* __restrict__ dst) {
    int e = blockIdx.x * blockDim.x + threadIdx.x;
    if (e >= EE) return;
    int d = dst[e];
    int p = atomicAdd(&g_pos[d], 1);
    g_csr[p] = src[e];
}

// ---------------- K1: h1 = x @ W1 (+ attention logits) ----------------
__global__ void __launch_bounds__(256) k1_gemm1(
    const float* __restrict__ x, const float* __restrict__ W1,
    const float* __restrict__ a1s, const float* __restrict__ a1d)
{
    __shared__ float sW[128 * 64];
    __shared__ float sA[128];
    for (int i = threadIdx.x; i < 128 * 64; i += blockDim.x) sW[i] = W1[i];
    for (int i = threadIdx.x; i < 128; i += blockDim.x)
        sA[i] = (i < 64) ? a1s[i] : a1d[i - 64];
    __syncthreads();

    int row = blockIdx.x * blockDim.x + threadIdx.x;
    if (row >= NN) return;

    float acc[64];
#pragma unroll
    for (int j = 0; j < 64; j++) acc[j] = 0.0f;

    const float4* x4 = (const float4*)(x + (size_t)row * 128);
#pragma unroll 1
    for (int kc = 0; kc < 32; kc++) {
        float4 xv = __ldg(x4 + kc);
#pragma unroll
        for (int t = 0; t < 4; t++) {
            float xs = (t == 0) ? xv.x : (t == 1) ? xv.y : (t == 2) ? xv.z : xv.w;
            const float4* wrow = (const float4*)(sW + (kc * 4 + t) * 64);
#pragma unroll
            for (int j4 = 0; j4 < 16; j4++) {
                float4 w = wrow[j4];
                acc[j4 * 4 + 0] += xs * w.x;
                acc[j4 * 4 + 1] += xs * w.y;
                acc[j4 * 4 + 2] += xs * w.z;
                acc[j4 * 4 + 3] += xs * w.w;
            }
        }
    }

    float4* h1o = (float4*)(g_h1 + (size_t)row * 64);
#pragma unroll
    for (int j4 = 0; j4 < 16; j4++)
        h1o[j4] = make_float4(acc[j4 * 4], acc[j4 * 4 + 1], acc[j4 * 4 + 2], acc[j4 * 4 + 3]);

#pragma unroll
    for (int h = 0; h < 8; h++) {
        float s = 0.0f, d = 0.0f;
#pragma unroll
        for (int q = 0; q < 8; q++) {
            s += acc[h * 8 + q] * sA[h * 8 + q];
            d += acc[h * 8 + q] * sA[64 + h * 8 + q];
        }
        g_as1[row * 8 + h] = s;
        g_ad1[row * 8 + h] = d;
    }
}

// ---------------- G1: warp-per-dst gather + softmax + bias + ELU ----------------
__global__ void __launch_bounds__(256) g1_gather(const float* __restrict__ b1) {
    int warp = (blockIdx.x * 256 + threadIdx.x) >> 5;
    int lane = threadIdx.x & 31;
    if (warp >= NN) return;
    int n = warp;
    int deg = g_deg[n];
    int off = g_off[n];
    float ad = (lane < 8) ? g_ad1[n * 8 + lane] : 0.0f;

    float2 acc = make_float2(0.0f, 0.0f);
    float den = 0.0f;
    int sreg = 0;

    for (int i = 0; i < deg; i++) {
        if ((i & 31) == 0) {
            sreg = (i + lane < deg) ? g_csr[off + i + lane] : 0;
        }
        int s = __shfl_sync(0xFFFFFFFFu, sreg, i & 31);
        float p = 0.0f;
        if (lane < 8) {
            float e = g_as1[s * 8 + lane] + ad;
            e = (e >= 0.0f) ? e : NEG_SLOPE * e;
            p = __expf(e);
        }
        p = __shfl_sync(0xFFFFFFFFu, p, lane >> 2);   // head of this lane's dims
        float2 v = *(const float2*)(g_h1 + (size_t)s * 64 + 2 * lane);
        acc.x += p * v.x;
        acc.y += p * v.y;
        den += p;
    }

    float inv = (den > 0.0f) ? (1.0f / den) : 0.0f;
    float r0 = acc.x * inv + b1[2 * lane];
    float r1 = acc.y * inv + b1[2 * lane + 1];
    r0 = (r0 > 0.0f) ? r0 : (__expf(r0) - 1.0f);
    r1 = (r1 > 0.0f) ? r1 : (__expf(r1) - 1.0f);
    *(float2*)(g_out1 + (size_t)n * 64 + 2 * lane) = make_float2(r0, r1);
}

// ---------------- K5: g2 = elu_h @ W2 (+ layer2 attention logits) ----------------
__global__ void __launch_bounds__(256) k5_gemm2(
    const float* __restrict__ W2, const float* __restrict__ a2s,
    const float* __restrict__ a2d)
{
    __shared__ float sW[64 * 16];
    __shared__ float sA[32];
    for (int i = threadIdx.x; i < 64 * 16; i += blockDim.x) sW[i] = W2[i];
    for (int i = threadIdx.x; i < 32; i += blockDim.x)
        sA[i] = (i < 16) ? a2s[i] : a2d[i - 16];
    __syncthreads();

    int row = blockIdx.x * blockDim.x + threadIdx.x;
    if (row >= NN) return;

    float acc[16];
#pragma unroll
    for (int j = 0; j < 16; j++) acc[j] = 0.0f;

    const float4* x4 = (const float4*)(g_out1 + (size_t)row * 64);
#pragma unroll 1
    for (int kc = 0; kc < 16; kc++) {
        float4 xv = x4[kc];
#pragma unroll
        for (int t = 0; t < 4; t++) {
            float xs = (t == 0) ? xv.x : (t == 1) ? xv.y : (t == 2) ? xv.z : xv.w;
            const float4* wrow = (const float4*)(sW + (kc * 4 + t) * 16);
#pragma unroll
            for (int j4 = 0; j4 < 4; j4++) {
                float4 w = wrow[j4];
                acc[j4 * 4 + 0] += xs * w.x;
                acc[j4 * 4 + 1] += xs * w.y;
                acc[j4 * 4 + 2] += xs * w.z;
                acc[j4 * 4 + 3] += xs * w.w;
            }
        }
    }

    float4* go = (float4*)(g_g2 + (size_t)row * 16);
#pragma unroll
    for (int j4 = 0; j4 < 4; j4++)
        go[j4] = make_float4(acc[j4 * 4], acc[j4 * 4 + 1], acc[j4 * 4 + 2], acc[j4 * 4 + 3]);

    float s = 0.0f, d = 0.0f;
#pragma unroll
    for (int j = 0; j < 16; j++) { s += acc[j] * sA[j]; d += acc[j] * sA[16 + j]; }
    g_as2[row] = s;
    g_ad2[row] = d;
}

// ---------------- G2: warp-per-dst gather (2 edges/iter) + log_softmax ----------------
__global__ void __launch_bounds__(256) g2_gather(const float* __restrict__ b2,
                                                 float* __restrict__ out) {
    int warp = (blockIdx.x * 256 + threadIdx.x) >> 5;
    int lane = threadIdx.x & 31;
    if (warp >= NN) return;
    int n = warp;
    int deg = g_deg[n];
    int off = g_off[n];
    int half = lane >> 4;      // which of 2 edges per iteration
    int d16 = lane & 15;       // output class
    float ad = g_ad2[n];

    float acc = 0.0f, den = 0.0f;

    for (int i = 0; i < deg; i += 2) {
        int idx = i + half;
        float p = 0.0f, v = 0.0f;
        if (idx < deg) {
            int s = g_csr[off + idx];
            if (d16 == 0) {
                float e = g_as2[s] + ad;
                e = (e >= 0.0f) ? e : NEG_SLOPE * e;
                p = __expf(e);
            }
            v = g_g2[(size_t)s * 16 + d16];
        }
        p = __shfl_sync(0xFFFFFFFFu, p, lane & 16);   // broadcast within half
        acc += p * v;
        den += p;
    }

    // combine the two halves
    acc += __shfl_xor_sync(0xFFFFFFFFu, acc, 16);
    den += __shfl_xor_sync(0xFFFFFFFFu, den, 16);

    float z = ((den > 0.0f) ? (acc / den) : 0.0f) + b2[d16];

    // log-softmax over 16 classes (within each 16-lane group)
    float m = z;
#pragma unroll
    for (int ofs = 1; ofs < 16; ofs <<= 1)
        m = fmaxf(m, __shfl_xor_sync(0xFFFFFFFFu, m, ofs));
    float sum = __expf(z - m);
#pragma unroll
    for (int ofs = 1; ofs < 16; ofs <<= 1)
        sum += __shfl_xor_sync(0xFFFFFFFFu, sum, ofs);
    float lse = m + logf(sum);

    if (lane < 16) out[(size_t)n * 16 + d16] = z - lse;
}

// ---------------- launcher ----------------
extern "C" void kernel_launch(void* const* d_in, const int* in_sizes, int n_in,
                              void* d_out, int out_size) {
    const float* x   = (const float*)d_in[0];
    const int*   ei  = (const int*)d_in[1];
    const float* W1  = (const float*)d_in[2];
    const float* a1s = (const float*)d_in[3];
    const float* a1d = (const float*)d_in[4];
    const float* b1  = (const float*)d_in[5];
    const float* W2  = (const float*)d_in[6];
    const float* a2s = (const float*)d_in[7];
    const float* a2d = (const float*)d_in[8];
    const float* b2  = (const float*)d_in[9];
    float* out = (float*)d_out;

    const int* src = ei;
    const int* dst = ei + EE;

    const int TB = 256;
    // CSR build
    k0_init<<<(NN + TB - 1) / TB, TB>>>();
    k_hist<<<(EE + TB - 1) / TB, TB>>>(dst);
    s1_scan<<<NBLK, SCAN_B>>>();
    s2_scan<<<1, 256>>>();
    s3_apply<<<(NN + TB - 1) / TB, TB>>>();
    k_scatter<<<(EE + TB - 1) / TB, TB>>>(src, dst);
    // layer 1
    k1_gemm1<<<(NN + TB - 1) / TB, TB>>>(x, W1, a1s, a1d);
    g1_gather<<<(NN * 32 + TB - 1) / TB, TB>>>(b1);
    // layer 2
    k5_gemm2<<<(NN + TB - 1) / TB, TB>>>(W2, a2s, a2d);
    g2_gather<<<(NN * 32 + TB - 1) / TB, TB>>>(b2, out);
}

// round 4
// speedup vs baseline: 2.7786x; 1.0920x over previous
#include <cuda_runtime.h>
#include <cuda_bf16.h>
#include <math.h>

#define NN 100000
#define EE 1600000
#define NEG_SLOPE 0.2f
#define SCAN_B 512
#define NBLK ((NN + SCAN_B - 1) / SCAN_B)   // 196

// ---------------- scratch (device globals) ----------------
__device__ float g_h1[NN * 64];     // layer1 GEMM output [N,H*D]
__device__ float g_as1[NN * 8];
__device__ float g_ad1[NN * 8];
__device__ float g_out1[NN * 64];   // layer1 final (ELU'd)
__device__ float g_g2[NN * 16];     // layer2 GEMM output
__device__ float g_as2[NN];
__device__ float g_ad2[NN];
__device__ int   g_deg[NN];
__device__ int   g_off[NN];
__device__ int   g_pos[NN];
__device__ int   g_csr[EE];         // src node ids, grouped by dst
__device__ int   g_bsum[NBLK];

// ---------------- K0: zero degree histogram ----------------
__global__ void k0_init() {
    int i = blockIdx.x * blockDim.x + threadIdx.x;
    if (i < NN) g_deg[i] = 0;
}

// ---------------- CSR build ----------------
__global__ void k_hist(const int* __restrict__ dst) {
    int e = blockIdx.x * blockDim.x + threadIdx.x;
    if (e < EE) atomicAdd(&g_deg[dst[e]], 1);
}

__global__ void s1_scan() {
    __shared__ int sd[SCAN_B];
    int i = blockIdx.x * SCAN_B + threadIdx.x;
    int v = (i < NN) ? g_deg[i] : 0;
    sd[threadIdx.x] = v;
    __syncthreads();
    for (int ofs = 1; ofs < SCAN_B; ofs <<= 1) {
        int t = (threadIdx.x >= ofs) ? sd[threadIdx.x - ofs] : 0;
        __syncthreads();
        sd[threadIdx.x] += t;
        __syncthreads();
    }
    if (i < NN) g_off[i] = sd[threadIdx.x] - v;           // exclusive within block
    if (threadIdx.x == SCAN_B - 1) g_bsum[blockIdx.x] = sd[threadIdx.x];
}

// s3 now also performs the cross-block scan (replaces old s2 kernel)
__global__ void s3_apply() {
    __shared__ int sbase;
    int b = blockIdx.x;
    if (threadIdx.x < 32) {
        int p = 0;
        for (int i = threadIdx.x; i < b; i += 32) p += g_bsum[i];
#pragma unroll
        for (int o = 16; o; o >>= 1) p += __shfl_xor_sync(0xFFFFFFFFu, p, o);
        if (threadIdx.x == 0) sbase = p;
    }
    __syncthreads();
    int i = b * SCAN_B + threadIdx.x;
    if (i < NN) {
        int o = g_off[i] + sbase;
        g_off[i] = o;
        g_pos[i] = o;
    }
}

__global__ void k_scatter(const int* __restrict__ src, const int* __restrict__ dst) {
    int e = blockIdx.x * blockDim.x + threadIdx.x;
    if (e >= EE) return;
    int d = dst[e];
    int p = atomicAdd(&g_pos[d], 1);
    g_csr[p] = src[e];
}

// ---------------- K1: h1 = x @ W1 (+ attention logits) ----------------
__global__ void __launch_bounds__(256) k1_gemm1(
    const float* __restrict__ x, const float* __restrict__ W1,
    const float* __restrict__ a1s, const float* __restrict__ a1d)
{
    __shared__ float sW[128 * 64];
    __shared__ float sA[128];
    for (int i = threadIdx.x; i < 128 * 64; i += blockDim.x) sW[i] = W1[i];
    for (int i = threadIdx.x; i < 128; i += blockDim.x)
        sA[i] = (i < 64) ? a1s[i] : a1d[i - 64];
    __syncthreads();

    int row = blockIdx.x * blockDim.x + threadIdx.x;
    if (row >= NN) return;

    float acc[64];
#pragma unroll
    for (int j = 0; j < 64; j++) acc[j] = 0.0f;

    const float4* x4 = (const float4*)(x + (size_t)row * 128);
#pragma unroll 1
    for (int kc = 0; kc < 32; kc++) {
        float4 xv = __ldg(x4 + kc);
#pragma unroll
        for (int t = 0; t < 4; t++) {
            float xs = (t == 0) ? xv.x : (t == 1) ? xv.y : (t == 2) ? xv.z : xv.w;
            const float4* wrow = (const float4*)(sW + (kc * 4 + t) * 64);
#pragma unroll
            for (int j4 = 0; j4 < 16; j4++) {
                float4 w = wrow[j4];
                acc[j4 * 4 + 0] += xs * w.x;
                acc[j4 * 4 + 1] += xs * w.y;
                acc[j4 * 4 + 2] += xs * w.z;
                acc[j4 * 4 + 3] += xs * w.w;
            }
        }
    }

    float4* h1o = (float4*)(g_h1 + (size_t)row * 64);
#pragma unroll
    for (int j4 = 0; j4 < 16; j4++)
        h1o[j4] = make_float4(acc[j4 * 4], acc[j4 * 4 + 1], acc[j4 * 4 + 2], acc[j4 * 4 + 3]);

#pragma unroll
    for (int h = 0; h < 8; h++) {
        float s = 0.0f, d = 0.0f;
#pragma unroll
        for (int q = 0; q < 8; q++) {
            s += acc[h * 8 + q] * sA[h * 8 + q];
            d += acc[h * 8 + q] * sA[64 + h * 8 + q];
        }
        g_as1[row * 8 + h] = s;
        g_ad1[row * 8 + h] = d;
    }
}

// ---------------- G1: warp-per-dst gather, 4-edge batched logits ----------------
__global__ void __launch_bounds__(256) g1_gather(const float* __restrict__ b1) {
    int warp = (blockIdx.x * 256 + threadIdx.x) >> 5;
    int lane = threadIdx.x & 31;
    if (warp >= NN) return;
    int n = warp;
    int deg = g_deg[n];
    int off = g_off[n];
    int h8 = lane & 7;            // head index in logit phase (lane = edge*8 + h8)
    int h4 = lane >> 2;           // head owning this lane's 2 dims
    float adf = g_ad1[n * 8 + h8];

    float2 acc = make_float2(0.0f, 0.0f);
    float den = 0.0f;

    for (int base = 0; base < deg; base += 32) {
        int idx = base + lane;
        int sreg = (idx < deg) ? g_csr[off + idx] : 0;
        int cnt = min(32, deg - base);
        for (int g = 0; g < cnt; g += 4) {
            // logits for edges base+g .. base+g+3 across all 32 lanes
            int le = g + (lane >> 3);
            int sl = __shfl_sync(0xFFFFFFFFu, sreg, le);
            float e = g_as1[sl * 8 + h8] + adf;
            e = (e >= 0.0f) ? e : NEG_SLOPE * e;
            float p = __expf(e);
            if (base + le >= deg) p = 0.0f;
#pragma unroll
            for (int j = 0; j < 4; j++) {
                int s = __shfl_sync(0xFFFFFFFFu, sreg, g + j);
                float pj = __shfl_sync(0xFFFFFFFFu, p, j * 8 + h4);
                float2 v = *(const float2*)(g_h1 + (size_t)s * 64 + 2 * lane);
                acc.x += pj * v.x;
                acc.y += pj * v.y;
                den += pj;
            }
        }
    }

    float inv = (den > 0.0f) ? (1.0f / den) : 0.0f;
    float r0 = acc.x * inv + b1[2 * lane];
    float r1 = acc.y * inv + b1[2 * lane + 1];
    r0 = (r0 > 0.0f) ? r0 : (__expf(r0) - 1.0f);
    r1 = (r1 > 0.0f) ? r1 : (__expf(r1) - 1.0f);
    *(float2*)(g_out1 + (size_t)n * 64 + 2 * lane) = make_float2(r0, r1);
}

// ---------------- K5: g2 = elu_h @ W2 (+ layer2 attention logits) ----------------
__global__ void __launch_bounds__(256) k5_gemm2(
    const float* __restrict__ W2, const float* __restrict__ a2s,
    const float* __restrict__ a2d)
{
    __shared__ float sW[64 * 16];
    __shared__ float sA[32];
    for (int i = threadIdx.x; i < 64 * 16; i += blockDim.x) sW[i] = W2[i];
    for (int i = threadIdx.x; i < 32; i += blockDim.x)
        sA[i] = (i < 16) ? a2s[i] : a2d[i - 16];
    __syncthreads();

    int row = blockIdx.x * blockDim.x + threadIdx.x;
    if (row >= NN) return;

    float acc[16];
#pragma unroll
    for (int j = 0; j < 16; j++) acc[j] = 0.0f;

    const float4* x4 = (const float4*)(g_out1 + (size_t)row * 64);
#pragma unroll 1
    for (int kc = 0; kc < 16; kc++) {
        float4 xv = x4[kc];
#pragma unroll
        for (int t = 0; t < 4; t++) {
            float xs = (t == 0) ? xv.x : (t == 1) ? xv.y : (t == 2) ? xv.z : xv.w;
            const float4* wrow = (const float4*)(sW + (kc * 4 + t) * 16);
#pragma unroll
            for (int j4 = 0; j4 < 4; j4++) {
                float4 w = wrow[j4];
                acc[j4 * 4 + 0] += xs * w.x;
                acc[j4 * 4 + 1] += xs * w.y;
                acc[j4 * 4 + 2] += xs * w.z;
                acc[j4 * 4 + 3] += xs * w.w;
            }
        }
    }

    float4* go = (float4*)(g_g2 + (size_t)row * 16);
#pragma unroll
    for (int j4 = 0; j4 < 4; j4++)
        go[j4] = make_float4(acc[j4 * 4], acc[j4 * 4 + 1], acc[j4 * 4 + 2], acc[j4 * 4 + 3]);

    float s = 0.0f, d = 0.0f;
#pragma unroll
    for (int j = 0; j < 16; j++) { s += acc[j] * sA[j]; d += acc[j] * sA[16 + j]; }
    g_as2[row] = s;
    g_ad2[row] = d;
}

// ---------------- G2: warp-per-dst gather, 32-edge batched logits ----------------
__global__ void __launch_bounds__(256) g2_gather(const float* __restrict__ b2,
                                                 float* __restrict__ out) {
    int warp = (blockIdx.x * 256 + threadIdx.x) >> 5;
    int lane = threadIdx.x & 31;
    if (warp >= NN) return;
    int n = warp;
    int deg = g_deg[n];
    int off = g_off[n];
    int half = lane >> 4;      // which of 2 edges per accumulation step
    int d16 = lane & 15;       // output class
    float ad = g_ad2[n];

    float acc = 0.0f, den = 0.0f;

    for (int base = 0; base < deg; base += 32) {
        int idx = base + lane;
        int sreg = (idx < deg) ? g_csr[off + idx] : 0;
        float e = g_as2[sreg] + ad;
        e = (e >= 0.0f) ? e : NEG_SLOPE * e;
        float p = __expf(e);
        if (idx >= deg) p = 0.0f;
        int cnt = min(32, deg - base);
        for (int g = 0; g < cnt; g += 2) {
            int s = __shfl_sync(0xFFFFFFFFu, sreg, g + half);
            float pj = __shfl_sync(0xFFFFFFFFu, p, g + half);
            float v = g_g2[(size_t)s * 16 + d16];
            acc += pj * v;
            den += pj;
        }
    }

    // combine the two halves
    acc += __shfl_xor_sync(0xFFFFFFFFu, acc, 16);
    den += __shfl_xor_sync(0xFFFFFFFFu, den, 16);

    float z = ((den > 0.0f) ? (acc / den) : 0.0f) + b2[d16];

    // log-softmax over 16 classes (within each 16-lane group)
    float m = z;
#pragma unroll
    for (int ofs = 1; ofs < 16; ofs <<= 1)
        m = fmaxf(m, __shfl_xor_sync(0xFFFFFFFFu, m, ofs));
    float sum = __expf(z - m);
#pragma unroll
    for (int ofs = 1; ofs < 16; ofs <<= 1)
        sum += __shfl_xor_sync(0xFFFFFFFFu, sum, ofs);
    float lse = m + logf(sum);

    if (lane < 16) out[(size_t)n * 16 + d16] = z - lse;
}

// ---------------- launcher ----------------
extern "C" void kernel_launch(void* const* d_in, const int* in_sizes, int n_in,
                              void* d_out, int out_size) {
    const float* x   = (const float*)d_in[0];
    const int*   ei  = (const int*)d_in[1];
    const float* W1  = (const float*)d_in[2];
    const float* a1s = (const float*)d_in[3];
    const float* a1d = (const float*)d_in[4];
    const float* b1  = (const float*)d_in[5];
    const float* W2  = (const float*)d_in[6];
    const float* a2s = (const float*)d_in[7];
    const float* a2d = (const float*)d_in[8];
    const float* b2  = (const float*)d_in[9];
    float* out = (float*)d_out;

    const int* src = ei;
    const int* dst = ei + EE;

    const int TB = 256;
    // CSR build
    k0_init<<<(NN + TB - 1) / TB, TB>>>();
    k_hist<<<(EE + TB - 1) / TB, TB>>>(dst);
    s1_scan<<<NBLK, SCAN_B>>>();
    s3_apply<<<NBLK, SCAN_B>>>();
    k_scatter<<<(EE + TB - 1) / TB, TB>>>(src, dst);
    // layer 1
    k1_gemm1<<<(NN + TB - 1) / TB, TB>>>(x, W1, a1s, a1d);
    g1_gather<<<(NN * 32 + TB - 1) / TB, TB>>>(b1);
    // layer 2
    k5_gemm2<<<(NN + TB - 1) / TB, TB>>>(W2, a2s, a2d);
    g2_gather<<<(NN * 32 + TB - 1) / TB, TB>>>(b2, out);
}